// round 5
// baseline (speedup 1.0000x reference)
#include <cuda_runtime.h>
#include <cuda_bf16.h>
#include <math.h>
#include <float.h>
#include <stdint.h>

#define BATCH 8
#define LSEQ 1024
#define DMODEL 768
#define D2V 1536
#define NSTATE 16
#define ROWS (BATCH*LSEQ)
#define K3 (3*LSEQ)

#define BM 128
#define BN 128
#define BK 32
#define STAGES 3
// stage: Ah 128*80 + Al 128*80 + Bh 32*256 + Bl 32*256 = 10240+10240+8192+8192
#define A_PITCH 80u
#define OFF_AL 10240u
#define OFF_BH 20480u
#define OFF_BL 28672u
#define STAGE_BYTES 36864u
#define SMEM_DYN (STAGES*STAGE_BYTES)

typedef __nv_bfloat16 bf16;

// ------------------------- device scratch -------------------------
__device__ float g_x   [ROWS*DMODEL];
__device__ float g_xp  [ROWS*D2V];
__device__ float g_xco [ROWS*D2V];
__device__ float g_dl  [ROWS*D2V];
__device__ float g_xr  [ROWS*D2V];
__device__ float g_rowsum[ROWS];
__device__ float g_rowsq [ROWS];
__device__ float g_mu  [BATCH];
__device__ float g_rsig[BATCH];
__device__ float g_s   [ROWS];

__device__ bf16 g_xnP_h [ROWS*DMODEL], g_xnP_l [ROWS*DMODEL];
__device__ bf16 g_xcaP_h[ROWS*D2V],    g_xcaP_l[ROWS*D2V];
__device__ bf16 g_xcoP_h[ROWS*D2V],    g_xcoP_l[ROWS*D2V];
__device__ bf16 g_prP_h [ROWS*D2V],    g_prP_l [ROWS*D2V];
__device__ bf16 g_WinS_h[DMODEL*D2V],  g_WinS_l[DMODEL*D2V];
__device__ bf16 g_WclS_h[D2V*D2V],     g_WclS_l[D2V*D2V];
__device__ bf16 g_fc1S_h[D2V*D2V],     g_fc1S_l[D2V*D2V];
__device__ bf16 g_WDS_h [DMODEL*D2V],  g_WDS_l [DMODEL*D2V];
__device__ bf16 g_WoS_h [D2V*DMODEL],  g_WoS_l [D2V*DMODEL];
__device__ bf16 g_cA_h  [LSEQ*K3],     g_cA_l  [LSEQ*K3];
__device__ bf16 g_cB_h  [(size_t)BATCH*K3*D2V];
__device__ bf16 g_cB_l  [(size_t)BATCH*K3*D2V];

// ------------------------- helpers -------------------------
__device__ __forceinline__ float siluf(float v){ return v / (1.f + expf(-v)); }
__device__ __forceinline__ float softplusf(float v){ return (v > 20.f) ? v : log1pf(expf(v)); }

__device__ __forceinline__ uint32_t smem_u32(const void* p){
    uint32_t a;
    asm("{ .reg .u64 t; cvta.to.shared.u64 t, %1; cvt.u32.u64 %0, t; }" : "=r"(a) : "l"(p));
    return a;
}
__device__ __forceinline__ void cpa16(uint32_t dst, const void* src){
    asm volatile("cp.async.cg.shared.global [%0], [%1], 16;" :: "r"(dst), "l"(src) : "memory");
}
#define CP_COMMIT() asm volatile("cp.async.commit_group;" ::: "memory")
#define CP_WAIT(n)  asm volatile("cp.async.wait_group %0;" :: "n"(n) : "memory")

__device__ __forceinline__ void ldsm4(uint32_t addr, uint32_t* r){
    asm volatile("ldmatrix.sync.aligned.m8n8.x4.shared.b16 {%0,%1,%2,%3}, [%4];"
        : "=r"(r[0]), "=r"(r[1]), "=r"(r[2]), "=r"(r[3]) : "r"(addr));
}
__device__ __forceinline__ void ldsm4t(uint32_t addr, uint32_t* r0, uint32_t* r1){
    asm volatile("ldmatrix.sync.aligned.m8n8.x4.trans.shared.b16 {%0,%1,%2,%3}, [%4];"
        : "=r"(r0[0]), "=r"(r0[1]), "=r"(r1[0]), "=r"(r1[1]) : "r"(addr));
}
__device__ __forceinline__ void mma16816(float* d, const uint32_t* a, const uint32_t* b){
    asm volatile("mma.sync.aligned.m16n8k16.row.col.f32.bf16.bf16.f32 "
        "{%0,%1,%2,%3}, {%4,%5,%6,%7}, {%8,%9}, {%0,%1,%2,%3};"
        : "+f"(d[0]), "+f"(d[1]), "+f"(d[2]), "+f"(d[3])
        : "r"(a[0]), "r"(a[1]), "r"(a[2]), "r"(a[3]), "r"(b[0]), "r"(b[1]));
}
__device__ __forceinline__ void splitf(float v, bf16& h, bf16& l){
    h = __float2bfloat16(v);
    l = __float2bfloat16(v - __bfloat162float(h));
}

// ------------------------- HMMA GEMM -------------------------
// C[M,N] = EPI(A[M,K] @ B[K,N] + biasN[n] + biasM[m]); A,B bf16 hi/lo.
template<int EPI, bool SPLIT>
__global__ void __launch_bounds__(256, 2) k_tc(
    const bf16* __restrict__ Ah, const bf16* __restrict__ Al,
    const bf16* __restrict__ Bh, const bf16* __restrict__ Bl,
    const float* __restrict__ biasN, const float* __restrict__ biasM,
    float* __restrict__ C, bf16* __restrict__ Ch, bf16* __restrict__ Cl,
    int K, int N, long sA, long sB, long sC)
{
    extern __shared__ char smem[];
    const int tid  = threadIdx.x;
    const int wid  = tid >> 5, lane = tid & 31;
    const int wm   = wid & 3,  wn = wid >> 2;       // warp tile: rows wm*32, cols wn*64
    const int row0 = blockIdx.y * BM;
    const int col0 = blockIdx.x * BN;
    Ah += (size_t)blockIdx.z * sA;  Al += (size_t)blockIdx.z * sA;
    Bh += (size_t)blockIdx.z * sB;  Bl += (size_t)blockIdx.z * sB;
    if (C) C += (size_t)blockIdx.z * sC;
    if (SPLIT){ Ch += (size_t)blockIdx.z * sC; Cl += (size_t)blockIdx.z * sC; }
    const int NK = K >> 5;
    const uint32_t sbase = smem_u32(smem);

    float acc[2][8][4];
    #pragma unroll
    for (int mi = 0; mi < 2; mi++)
        #pragma unroll
        for (int nj = 0; nj < 8; nj++)
            #pragma unroll
            for (int q = 0; q < 4; q++) acc[mi][nj][q] = 0.f;

    // ---- stage fill: A 128x32 (h,l) rows padded to 80B; B 32x128 (h,l) 256B rows, XOR swizzle
    auto fill = [&](int kc, int s){
        uint32_t st = sbase + (uint32_t)s * STAGE_BYTES;
        const bf16* ap[2] = { Ah, Al };
        #pragma unroll
        for (int arr = 0; arr < 2; arr++){
            uint32_t base = st + arr * OFF_AL;
            #pragma unroll
            for (int it = 0; it < 2; it++){
                int id = tid + it * 256;            // 0..511
                int r = id >> 2, u = id & 3;
                cpa16(base + r * A_PITCH + u * 16,
                      ap[arr] + (size_t)(row0 + r) * K + kc * BK + u * 8);
            }
        }
        const bf16* bp[2] = { Bh, Bl };
        #pragma unroll
        for (int arr = 0; arr < 2; arr++){
            uint32_t base = st + OFF_BH + arr * (OFF_BL - OFF_BH);
            #pragma unroll
            for (int it = 0; it < 2; it++){
                int id = tid + it * 256;            // 0..511
                int k = id >> 4, u = id & 15;
                cpa16(base + k * 256 + (((uint32_t)(u ^ (k & 7))) << 4),
                      bp[arr] + (size_t)(kc * BK + k) * N + col0 + u * 8);
            }
        }
        CP_COMMIT();
    };

    fill(0, 0);
    fill(1, 1);

    for (int kc = 0; kc < NK; kc++){
        int s = kc % STAGES;
        CP_WAIT(1);
        __syncthreads();
        if (kc + 2 < NK) fill(kc + 2, (kc + 2) % STAGES);
        else CP_COMMIT();

        uint32_t aAh = sbase + (uint32_t)s * STAGE_BYTES;
        uint32_t aAl = aAh + OFF_AL;
        uint32_t aBh = aAh + OFF_BH;
        uint32_t aBl = aAh + OFF_BL;

        #pragma unroll
        for (int ks = 0; ks < 2; ks++){
            uint32_t ah[2][4], al[2][4];
            const int arow = wm * 32 + (lane & 15);
            const int au   = 2 * ks + (lane >> 4);
            #pragma unroll
            for (int mi = 0; mi < 2; mi++){
                int r = arow + mi * 16;
                uint32_t off = r * A_PITCH + au * 16;
                ldsm4(aAh + off, ah[mi]);
                ldsm4(aAl + off, al[mi]);
            }
            const int bk = ks * 16 + (lane & 15);
            // hi-B: hh + lh passes, low register pressure (b-frags live per p)
            #pragma unroll
            for (int p = 0; p < 4; p++){
                int u = wn * 8 + p * 2 + (lane >> 4);
                uint32_t off = bk * 256 + (((uint32_t)(u ^ (bk & 7))) << 4);
                uint32_t b0[2], b1[2];
                ldsm4t(aBh + off, b0, b1);
                mma16816(acc[0][2*p],   ah[0], b0);
                mma16816(acc[0][2*p+1], ah[0], b1);
                mma16816(acc[1][2*p],   ah[1], b0);
                mma16816(acc[1][2*p+1], ah[1], b1);
                mma16816(acc[0][2*p],   al[0], b0);
                mma16816(acc[0][2*p+1], al[0], b1);
                mma16816(acc[1][2*p],   al[1], b0);
                mma16816(acc[1][2*p+1], al[1], b1);
            }
            // lo-B: hl pass
            #pragma unroll
            for (int p = 0; p < 4; p++){
                int u = wn * 8 + p * 2 + (lane >> 4);
                uint32_t off = bk * 256 + (((uint32_t)(u ^ (bk & 7))) << 4);
                uint32_t b0[2], b1[2];
                ldsm4t(aBl + off, b0, b1);
                mma16816(acc[0][2*p],   ah[0], b0);
                mma16816(acc[0][2*p+1], ah[0], b1);
                mma16816(acc[1][2*p],   ah[1], b0);
                mma16816(acc[1][2*p+1], ah[1], b1);
            }
        }
    }

    // ---- epilogue: acc -> smem (padded) -> global
    __syncthreads();
    float* sf = (float*)smem;
    {
        const int mrow = wm * 32 + (lane >> 2);
        const int ncol = wn * 64 + (lane & 3) * 2;
        #pragma unroll
        for (int mi = 0; mi < 2; mi++)
            #pragma unroll
            for (int nj = 0; nj < 8; nj++){
                int m = mrow + mi * 16, n = ncol + nj * 8;
                *(float2*)&sf[(size_t)m * 132 + n]       = make_float2(acc[mi][nj][0], acc[mi][nj][1]);
                *(float2*)&sf[(size_t)(m + 8) * 132 + n] = make_float2(acc[mi][nj][2], acc[mi][nj][3]);
            }
    }
    __syncthreads();

    for (int i = tid; i < BM * (BN / 4); i += 256){
        int r = i >> 5, c = (i & 31) * 4;
        float4 v = *(float4*)&sf[(size_t)r * 132 + c];
        float bm = biasM ? __ldg(biasM + row0 + r) : 0.f;
        float vv[4] = { v.x, v.y, v.z, v.w };
        #pragma unroll
        for (int j = 0; j < 4; j++){
            float t = vv[j] + bm + (biasN ? __ldg(biasN + col0 + c + j) : 0.f);
            if (EPI == 1) t = siluf(t);
            else if (EPI == 2) t = softplusf(t);
            vv[j] = t;
        }
        size_t o = (size_t)(row0 + r) * N + col0 + c;
        if (C) *(float4*)(C + o) = make_float4(vv[0], vv[1], vv[2], vv[3]);
        if (SPLIT){
            bf16 hh[4], ll[4];
            #pragma unroll
            for (int j = 0; j < 4; j++) splitf(vv[j], hh[j], ll[j]);
            *(uint2*)(Ch + o) = *(uint2*)hh;
            *(uint2*)(Cl + o) = *(uint2*)ll;
        }
    }
}

// ------------------------- aux kernels -------------------------
__global__ void k_embed(const int* __restrict__ ids, const float* __restrict__ emb)
{
    int row = blockIdx.x;
    int id  = ids[row];
    const float* src = emb + (size_t)id * DMODEL;
    float s = 0.f, ss = 0.f;
    for (int d = threadIdx.x; d < DMODEL; d += blockDim.x){
        float v = __ldg(src + d);
        g_x[(size_t)row * DMODEL + d] = v;
        s += v; ss += v * v;
    }
    __shared__ float sh[64];
    int lane = threadIdx.x & 31, w = threadIdx.x >> 5;
    #pragma unroll
    for (int o = 16; o; o >>= 1){
        s  += __shfl_down_sync(0xffffffffu, s,  o);
        ss += __shfl_down_sync(0xffffffffu, ss, o);
    }
    if (!lane){ sh[w] = s; sh[32 + w] = ss; }
    __syncthreads();
    if (threadIdx.x == 0){
        float S = 0.f, SS = 0.f;
        int nw = blockDim.x >> 5;
        for (int i = 0; i < nw; i++){ S += sh[i]; SS += sh[32 + i]; }
        g_rowsum[row] = S; g_rowsq[row] = SS;
    }
}

__global__ void k_samplestats()
{
    int b = blockIdx.x;
    float s = 0.f, ss = 0.f;
    for (int r = threadIdx.x; r < LSEQ; r += blockDim.x){
        s += g_rowsum[b * LSEQ + r]; ss += g_rowsq[b * LSEQ + r];
    }
    __shared__ float sh[64];
    int lane = threadIdx.x & 31, w = threadIdx.x >> 5;
    #pragma unroll
    for (int o = 16; o; o >>= 1){
        s  += __shfl_down_sync(0xffffffffu, s,  o);
        ss += __shfl_down_sync(0xffffffffu, ss, o);
    }
    if (!lane){ sh[w] = s; sh[32 + w] = ss; }
    __syncthreads();
    if (threadIdx.x == 0){
        float S = 0.f, SS = 0.f;
        int nw = blockDim.x >> 5;
        for (int i = 0; i < nw; i++){ S += sh[i]; SS += sh[32 + i]; }
        float inv = 1.f / ((float)LSEQ * (float)DMODEL);
        float mu  = S * inv;
        float var = SS * inv - mu * mu;
        g_mu[b]   = mu;
        g_rsig[b] = rsqrtf(var + 1e-5f);
    }
}

__global__ void k_norm(const float* __restrict__ rms_w)
{
    int row = blockIdx.x;
    int b = row >> 10;
    float mu = g_mu[b], rs = g_rsig[b];
    float msq = rs * rs * (g_rowsq[row] - 2.f * mu * g_rowsum[row] + (float)DMODEL * mu * mu) / (float)DMODEL;
    float a = rs * rsqrtf(msq + 1e-5f);
    const float* xr = g_x + (size_t)row * DMODEL;
    for (int d = threadIdx.x; d < DMODEL; d += blockDim.x){
        float v = (xr[d] - mu) * a * rms_w[d];
        bf16 h, l; splitf(v, h, l);
        g_xnP_h[(size_t)row * DMODEL + d] = h;
        g_xnP_l[(size_t)row * DMODEL + d] = l;
    }
}

__global__ void k_wsplit(const float* __restrict__ W, bf16* __restrict__ Wh, bf16* __restrict__ Wl)
{
    size_t i4 = (size_t)blockIdx.x * blockDim.x + threadIdx.x;
    float4 v = ((const float4*)W)[i4];
    bf16 hh[4], ll[4];
    splitf(v.x, hh[0], ll[0]); splitf(v.y, hh[1], ll[1]);
    splitf(v.z, hh[2], ll[2]); splitf(v.w, hh[3], ll[3]);
    *(uint2*)(Wh + i4 * 4) = *(uint2*)hh;
    *(uint2*)(Wl + i4 * 4) = *(uint2*)ll;
}

// conv A repack: cA[o][k*1024+i] = conv_w[o][3i+k]
__global__ void k_convA(const float* __restrict__ cw)
{
    int o = blockIdx.y;
    int i = blockIdx.x * 256 + threadIdx.x;
    #pragma unroll
    for (int k = 0; k < 3; k++){
        float v = cw[(size_t)o * K3 + 3 * i + k];
        bf16 h, l; splitf(v, h, l);
        size_t off = (size_t)o * K3 + k * 1024 + i;
        g_cA_h[off] = h; g_cA_l[off] = l;
    }
}

// conv B gather (vectorized): cB[b][k*1024+i][t] = xp[b][i][t+k-1]
__global__ void k_convB()
{
    int t4 = threadIdx.x * 4;        // 384 threads * 4 = 1536
    int i  = blockIdx.x;             // 1024
    int zk = blockIdx.y;             // 24
    int b = zk / 3, k = zk % 3;
    const float* src = g_xp + ((size_t)(b * LSEQ) + i) * D2V;
    bf16 hh[4], ll[4];
    #pragma unroll
    for (int j = 0; j < 4; j++){
        int tt = t4 + j + k - 1;
        float v = (tt >= 0 && tt < D2V) ? src[tt] : 0.f;
        splitf(v, hh[j], ll[j]);
    }
    size_t o = (size_t)b * K3 * D2V + (size_t)(k * 1024 + i) * D2V + t4;
    *(uint2*)(g_cB_h + o) = *(uint2*)hh;
    *(uint2*)(g_cB_l + o) = *(uint2*)ll;
}

__global__ void k_bcs(const float* __restrict__ w2, const float* __restrict__ b2,
                      const float* __restrict__ w3, const float* __restrict__ b3)
{
    int row = blockIdx.x;
    const float* xr = g_xco + (size_t)row * D2V;
    float ab[NSTATE], ac[NSTATE];
    #pragma unroll
    for (int n = 0; n < NSTATE; n++){ ab[n] = 0.f; ac[n] = 0.f; }
    for (int k = threadIdx.x; k < D2V; k += blockDim.x){
        float xv = xr[k];
        const float4* q2 = (const float4*)(w2 + (size_t)k * NSTATE);
        const float4* q3 = (const float4*)(w3 + (size_t)k * NSTATE);
        #pragma unroll
        for (int q = 0; q < 4; q++){
            float4 a = q2[q], c = q3[q];
            ab[4*q+0] += xv*a.x; ab[4*q+1] += xv*a.y; ab[4*q+2] += xv*a.z; ab[4*q+3] += xv*a.w;
            ac[4*q+0] += xv*c.x; ac[4*q+1] += xv*c.y; ac[4*q+2] += xv*c.z; ac[4*q+3] += xv*c.w;
        }
    }
    __shared__ float shb[NSTATE], shc[NSTATE];
    if (threadIdx.x < NSTATE){ shb[threadIdx.x] = 0.f; shc[threadIdx.x] = 0.f; }
    __syncthreads();
    int lane = threadIdx.x & 31;
    #pragma unroll
    for (int n = 0; n < NSTATE; n++){
        float vb = ab[n], vc = ac[n];
        #pragma unroll
        for (int o = 16; o; o >>= 1){
            vb += __shfl_down_sync(0xffffffffu, vb, o);
            vc += __shfl_down_sync(0xffffffffu, vc, o);
        }
        if (lane == 0){ atomicAdd(&shb[n], vb); atomicAdd(&shc[n], vc); }
    }
    __syncthreads();
    if (threadIdx.x == 0){
        float s = 0.f;
        #pragma unroll
        for (int n = 0; n < NSTATE; n++) s += (shb[n] + b2[n]) * (shc[n] + b3[n]);
        g_s[row] = s;
    }
}

__global__ void k_prod()
{
    size_t i4 = (size_t)blockIdx.x * blockDim.x + threadIdx.x;
    int row = (int)(i4 / (D2V / 4));
    float sv = g_s[row];
    float4 xo = ((const float4*)g_xco)[i4];
    float4 dl = ((const float4*)g_dl )[i4];
    float4 xr = ((const float4*)g_xr )[i4];
    float r0 = siluf(xo.x*dl.x*sv) * xr.x;
    float r1 = siluf(xo.y*dl.y*sv) * xr.y;
    float r2 = siluf(xo.z*dl.z*sv) * xr.z;
    float r3 = siluf(xo.w*dl.w*sv) * xr.w;
    bf16 hh[4], ll[4];
    splitf(r0, hh[0], ll[0]); splitf(r1, hh[1], ll[1]);
    splitf(r2, hh[2], ll[2]); splitf(r3, hh[3], ll[3]);
    *(uint2*)(g_prP_h + i4*4) = *(uint2*)hh;
    *(uint2*)(g_prP_l + i4*4) = *(uint2*)ll;
}

__global__ void k_maxpool(const float* __restrict__ out, float* __restrict__ pooled)
{
    int b = blockIdx.y;
    int d = blockIdx.x * blockDim.x + threadIdx.x;
    if (d >= DMODEL) return;
    const float* p = out + (size_t)b * LSEQ * DMODEL + d;
    float m = -FLT_MAX;
    for (int l = 0; l < LSEQ; l++) m = fmaxf(m, p[(size_t)l * DMODEL]);
    pooled[b * DMODEL + d] = m;
}

// ------------------------- launch -------------------------
extern "C" void kernel_launch(void* const* d_in, const int* in_sizes, int n_in,
                              void* d_out, int out_size)
{
    const int*   ids    = (const int*)  d_in[0];
    const float* emb    = (const float*)d_in[1];
    const float* rms_w  = (const float*)d_in[2];
    const float* W_in   = (const float*)d_in[3];
    const float* b_in   = (const float*)d_in[4];
    const float* conv_w = (const float*)d_in[5];
    const float* conv_b = (const float*)d_in[6];
    const float* W_cl   = (const float*)d_in[7];
    const float* b_cl   = (const float*)d_in[8];
    const float* fc1_w  = (const float*)d_in[9];
    const float* fc1_b  = (const float*)d_in[10];
    const float* fc2_w  = (const float*)d_in[11];
    const float* fc2_b  = (const float*)d_in[12];
    const float* fc3_w  = (const float*)d_in[13];
    const float* fc3_b  = (const float*)d_in[14];
    const float* W_D    = (const float*)d_in[16];
    const float* b_D    = (const float*)d_in[17];
    const float* W_out  = (const float*)d_in[18];
    const float* b_out  = (const float*)d_in[19];
    float* out = (float*)d_out;

    cudaFuncSetAttribute(k_tc<0,false>, cudaFuncAttributeMaxDynamicSharedMemorySize, SMEM_DYN);
    cudaFuncSetAttribute(k_tc<0,true >, cudaFuncAttributeMaxDynamicSharedMemorySize, SMEM_DYN);
    cudaFuncSetAttribute(k_tc<1,false>, cudaFuncAttributeMaxDynamicSharedMemorySize, SMEM_DYN);
    cudaFuncSetAttribute(k_tc<1,true >, cudaFuncAttributeMaxDynamicSharedMemorySize, SMEM_DYN);
    cudaFuncSetAttribute(k_tc<2,false>, cudaFuncAttributeMaxDynamicSharedMemorySize, SMEM_DYN);

    bf16 *xnh, *xnl, *xcah, *xcal, *xcoh, *xcol, *prh, *prl;
    bf16 *winh, *winl, *wclh, *wcll, *f1h, *f1l, *wdh, *wdl, *woh, *wol;
    bf16 *cah, *cal, *cbh, *cbl;
    float *pxp, *pxco, *pdl, *pxr;
    cudaGetSymbolAddress((void**)&xnh,  g_xnP_h);  cudaGetSymbolAddress((void**)&xnl,  g_xnP_l);
    cudaGetSymbolAddress((void**)&xcah, g_xcaP_h); cudaGetSymbolAddress((void**)&xcal, g_xcaP_l);
    cudaGetSymbolAddress((void**)&xcoh, g_xcoP_h); cudaGetSymbolAddress((void**)&xcol, g_xcoP_l);
    cudaGetSymbolAddress((void**)&prh,  g_prP_h);  cudaGetSymbolAddress((void**)&prl,  g_prP_l);
    cudaGetSymbolAddress((void**)&winh, g_WinS_h); cudaGetSymbolAddress((void**)&winl, g_WinS_l);
    cudaGetSymbolAddress((void**)&wclh, g_WclS_h); cudaGetSymbolAddress((void**)&wcll, g_WclS_l);
    cudaGetSymbolAddress((void**)&f1h,  g_fc1S_h); cudaGetSymbolAddress((void**)&f1l,  g_fc1S_l);
    cudaGetSymbolAddress((void**)&wdh,  g_WDS_h);  cudaGetSymbolAddress((void**)&wdl,  g_WDS_l);
    cudaGetSymbolAddress((void**)&woh,  g_WoS_h);  cudaGetSymbolAddress((void**)&wol,  g_WoS_l);
    cudaGetSymbolAddress((void**)&cah,  g_cA_h);   cudaGetSymbolAddress((void**)&cal,  g_cA_l);
    cudaGetSymbolAddress((void**)&cbh,  g_cB_h);   cudaGetSymbolAddress((void**)&cbl,  g_cB_l);
    cudaGetSymbolAddress((void**)&pxp,  g_xp);
    cudaGetSymbolAddress((void**)&pxco, g_xco);
    cudaGetSymbolAddress((void**)&pdl,  g_dl);
    cudaGetSymbolAddress((void**)&pxr,  g_xr);

    // weight splits (natural [K][N] layout)
    k_wsplit<<<(DMODEL*D2V/4)/256, 256>>>(W_in,  winh, winl);
    k_wsplit<<<(D2V*D2V/4)/256,    256>>>(W_cl,  wclh, wcll);
    k_wsplit<<<(D2V*D2V/4)/256,    256>>>(fc1_w, f1h,  f1l);
    k_wsplit<<<(DMODEL*D2V/4)/256, 256>>>(W_D,   wdh,  wdl);
    k_wsplit<<<(D2V*DMODEL/4)/256, 256>>>(W_out, woh,  wol);
    k_convA<<<dim3(LSEQ/256, LSEQ), 256>>>(conv_w);

    // embed + norms
    k_embed<<<ROWS, 256>>>(ids, emb);
    k_samplestats<<<BATCH, 256>>>();
    k_norm<<<ROWS, 256>>>(rms_w);

    // GEMM1: xp = xn @ W_in + b_in
    k_tc<0,false><<<dim3(D2V/BN, ROWS/BM, 1), 256, SMEM_DYN>>>(
        xnh, xnl, winh, winl, b_in, nullptr, pxp, nullptr, nullptr,
        DMODEL, D2V, 0, 0, 0);

    // conv operand gather (vectorized, k-major)
    k_convB<<<dim3(LSEQ, 3*BATCH), 384>>>();

    // GEMM2 (conv): xca = silu(cA @ cB + conv_b[row]), split-only output
    k_tc<1,true><<<dim3(D2V/BN, LSEQ/BM, BATCH), 256, SMEM_DYN>>>(
        cah, cal, cbh, cbl, nullptr, conv_b, nullptr, xcah, xcal,
        K3, D2V, 0, (long)K3*D2V, (long)LSEQ*D2V);

    // GEMM3: xco = xca @ W_cl + b_cl (float + split)
    k_tc<0,true><<<dim3(D2V/BN, ROWS/BM, 1), 256, SMEM_DYN>>>(
        xcah, xcal, wclh, wcll, b_cl, nullptr, pxco, xcoh, xcol,
        D2V, D2V, 0, 0, 0);

    // GEMM4: delta = softplus(xco @ fc1 + b1)
    k_tc<2,false><<<dim3(D2V/BN, ROWS/BM, 1), 256, SMEM_DYN>>>(
        xcoh, xcol, f1h, f1l, fc1_b, nullptr, pdl, nullptr, nullptr,
        D2V, D2V, 0, 0, 0);

    // s[row] = sum_n Bm*Cm
    k_bcs<<<ROWS, 256>>>(fc2_w, fc2_b, fc3_w, fc3_b);

    // GEMM5: x_res = silu(xn @ W_D + b_D)
    k_tc<1,false><<<dim3(D2V/BN, ROWS/BM, 1), 256, SMEM_DYN>>>(
        xnh, xnl, wdh, wdl, b_D, nullptr, pxr, nullptr, nullptr,
        DMODEL, D2V, 0, 0, 0);

    // prod = silu(xco*delta*s) * x_res  (split for GEMM6)
    k_prod<<<(ROWS * D2V / 4) / 256, 256>>>();

    // GEMM6: out = prod @ W_out + b_out
    k_tc<0,false><<<dim3(DMODEL/BN, ROWS/BM, 1), 256, SMEM_DYN>>>(
        prh, prl, woh, wol, b_out, nullptr, out, nullptr, nullptr,
        D2V, DMODEL, 0, 0, 0);

    if (out_size >= ROWS * DMODEL + BATCH * DMODEL)
        k_maxpool<<<dim3((DMODEL + 255) / 256, BATCH), 256>>>(out, out + (size_t)ROWS * DMODEL);
}

// round 6
// speedup vs baseline: 1.6876x; 1.6876x over previous
#include <cuda_runtime.h>
#include <cuda_bf16.h>
#include <math.h>
#include <float.h>
#include <stdint.h>

#define BATCH 8
#define LSEQ 1024
#define DMODEL 768
#define D2V 1536
#define N2X 3072
#define NSTATE 16
#define ROWS (BATCH*LSEQ)
#define K3 (3*LSEQ)

#define BM 128
#define BN 128
#define STAGES 3
#define STAGE_BYTES 65536u
#define SMEM_DYN (STAGES*STAGE_BYTES)

typedef __nv_bfloat16 bf16;

// ------------------------- device scratch -------------------------
__device__ float g_x   [ROWS*DMODEL];
__device__ float g_xpr [(size_t)ROWS*N2X];   // cols 0-1535: xp ; cols 1536-3071: raw xn@W_D+b_D
__device__ float g_xco [ROWS*D2V];
__device__ float g_dl  [ROWS*D2V];
__device__ float g_rowsum[ROWS];
__device__ float g_rowsq [ROWS];
__device__ float g_mu  [BATCH];
__device__ float g_rsig[BATCH];
__device__ float g_s   [ROWS];
__device__ float g_b15 [N2X];

__device__ bf16 g_xnP_h [ROWS*DMODEL], g_xnP_l [ROWS*DMODEL];
__device__ bf16 g_xcaP_h[ROWS*D2V],    g_xcaP_l[ROWS*D2V];
__device__ bf16 g_xcoP_h[ROWS*D2V],    g_xcoP_l[ROWS*D2V];
__device__ bf16 g_prP_h [ROWS*D2V],    g_prP_l [ROWS*D2V];
__device__ bf16 g_W15_h [DMODEL*N2X],  g_W15_l [DMODEL*N2X];   // [768][3072] = W_in | W_D
__device__ bf16 g_WclS_h[D2V*D2V],     g_WclS_l[D2V*D2V];
__device__ bf16 g_fc1S_h[D2V*D2V],     g_fc1S_l[D2V*D2V];
__device__ bf16 g_WoS_h [D2V*DMODEL],  g_WoS_l [D2V*DMODEL];
__device__ bf16 g_cA_h  [LSEQ*K3],     g_cA_l  [LSEQ*K3];
__device__ bf16 g_cB_h  [(size_t)BATCH*K3*D2V];
__device__ bf16 g_cB_l  [(size_t)BATCH*K3*D2V];

// ------------------------- helpers -------------------------
__device__ __forceinline__ float siluf(float v){ return v / (1.f + expf(-v)); }
__device__ __forceinline__ float softplusf(float v){ return (v > 20.f) ? v : log1pf(expf(v)); }

__device__ __forceinline__ uint32_t smem_u32(const void* p){
    uint32_t a;
    asm("{ .reg .u64 t; cvta.to.shared.u64 t, %1; cvt.u32.u64 %0, t; }" : "=r"(a) : "l"(p));
    return a;
}
__device__ __forceinline__ void cpa16(uint32_t dst, const void* src){
    asm volatile("cp.async.cg.shared.global [%0], [%1], 16;" :: "r"(dst), "l"(src) : "memory");
}
#define CP_COMMIT() asm volatile("cp.async.commit_group;" ::: "memory")
#define CP_WAIT(n)  asm volatile("cp.async.wait_group %0;" :: "n"(n) : "memory")

__device__ __forceinline__ void ldsm4(uint32_t addr, uint32_t* r){
    asm volatile("ldmatrix.sync.aligned.m8n8.x4.shared.b16 {%0,%1,%2,%3}, [%4];"
        : "=r"(r[0]), "=r"(r[1]), "=r"(r[2]), "=r"(r[3]) : "r"(addr));
}
__device__ __forceinline__ void ldsm4t(uint32_t addr, uint32_t* r0, uint32_t* r1){
    asm volatile("ldmatrix.sync.aligned.m8n8.x4.trans.shared.b16 {%0,%1,%2,%3}, [%4];"
        : "=r"(r0[0]), "=r"(r0[1]), "=r"(r1[0]), "=r"(r1[1]) : "r"(addr));
}
__device__ __forceinline__ void mma16816(float* d, const uint32_t* a, const uint32_t* b){
    asm volatile("mma.sync.aligned.m16n8k16.row.col.f32.bf16.bf16.f32 "
        "{%0,%1,%2,%3}, {%4,%5,%6,%7}, {%8,%9}, {%0,%1,%2,%3};"
        : "+f"(d[0]), "+f"(d[1]), "+f"(d[2]), "+f"(d[3])
        : "r"(a[0]), "r"(a[1]), "r"(a[2]), "r"(a[3]), "r"(b[0]), "r"(b[1]));
}
__device__ __forceinline__ void splitf(float v, bf16& h, bf16& l){
    h = __float2bfloat16(v);
    l = __float2bfloat16(v - __bfloat162float(h));
}

// ------------------------- HMMA GEMM (R4-proven core) -------------------------
// C[M,N] = EPI(A[M,K] @ B[K,N] + biasN[n] + biasM[m]); A,B bf16 hi/lo.
template<int EPI, bool SPLIT>
__global__ void __launch_bounds__(256, 1) k_tc(
    const bf16* __restrict__ Ah, const bf16* __restrict__ Al,
    const bf16* __restrict__ Bh, const bf16* __restrict__ Bl,
    const float* __restrict__ biasN, const float* __restrict__ biasM,
    float* __restrict__ C, bf16* __restrict__ Ch, bf16* __restrict__ Cl,
    int K, int N, long sA, long sB, long sC)
{
    extern __shared__ char smem[];
    const int tid  = threadIdx.x;
    const int wid  = tid >> 5, lane = tid & 31;
    const int wm   = wid & 3,  wn = wid >> 2;
    const int row0 = blockIdx.y * BM;
    const int col0 = blockIdx.x * BN;
    Ah += (size_t)blockIdx.z * sA;  Al += (size_t)blockIdx.z * sA;
    Bh += (size_t)blockIdx.z * sB;  Bl += (size_t)blockIdx.z * sB;
    if (C) C += (size_t)blockIdx.z * sC;
    if (SPLIT){ Ch += (size_t)blockIdx.z * sC; Cl += (size_t)blockIdx.z * sC; }
    const int NK = K >> 6;
    const uint32_t sbase = smem_u32(smem);

    float acc[2][8][4];
    #pragma unroll
    for (int mi = 0; mi < 2; mi++)
        #pragma unroll
        for (int nj = 0; nj < 8; nj++)
            #pragma unroll
            for (int q = 0; q < 4; q++) acc[mi][nj][q] = 0.f;

    auto fill = [&](int kc, int s){
        uint32_t st = sbase + (uint32_t)s * STAGE_BYTES;
        const bf16* ap[2] = { Ah, Al };
        #pragma unroll
        for (int arr = 0; arr < 2; arr++){
            uint32_t base = st + arr * 16384u;
            #pragma unroll
            for (int it = 0; it < 4; it++){
                int id = tid + it * 256;
                int r = id >> 3, u = id & 7;
                cpa16(base + r * 128 + (((uint32_t)(u ^ (r & 7))) << 4),
                      ap[arr] + (size_t)(row0 + r) * K + kc * 64 + u * 8);
            }
        }
        const bf16* bp[2] = { Bh, Bl };
        #pragma unroll
        for (int arr = 0; arr < 2; arr++){
            uint32_t base = st + 32768u + arr * 16384u;
            #pragma unroll
            for (int it = 0; it < 4; it++){
                int id = tid + it * 256;
                int k = id >> 4, u = id & 15;
                cpa16(base + k * 256 + (((uint32_t)(u ^ (k & 7))) << 4),
                      bp[arr] + (size_t)(kc * 64 + k) * N + col0 + u * 8);
            }
        }
        CP_COMMIT();
    };

    fill(0, 0);
    if (NK > 1) fill(1, 1); else CP_COMMIT();

    for (int kc = 0; kc < NK; kc++){
        int s = kc % STAGES;
        CP_WAIT(1);
        __syncthreads();

        uint32_t aAh = sbase + (uint32_t)s * STAGE_BYTES;
        uint32_t aAl = aAh + 16384u;
        uint32_t aBh = aAh + 32768u;
        uint32_t aBl = aAh + 49152u;

        #pragma unroll
        for (int ks = 0; ks < 4; ks++){
            uint32_t ah[2][4], al[2][4], bb[8][2];
            const int arow = wm * 32 + (lane & 15);
            const int au   = 2 * ks + (lane >> 4);
            #pragma unroll
            for (int mi = 0; mi < 2; mi++){
                int r = arow + mi * 16;
                uint32_t off = r * 128 + (((uint32_t)(au ^ (r & 7))) << 4);
                ldsm4(aAh + off, ah[mi]);
                ldsm4(aAl + off, al[mi]);
            }
            const int bk = ks * 16 + (lane & 15);
            #pragma unroll
            for (int p = 0; p < 4; p++){
                int u = wn * 8 + p * 2 + (lane >> 4);
                uint32_t off = bk * 256 + (((uint32_t)(u ^ (bk & 7))) << 4);
                ldsm4t(aBh + off, bb[2*p], bb[2*p+1]);
            }
            #pragma unroll
            for (int mi = 0; mi < 2; mi++)
                #pragma unroll
                for (int nj = 0; nj < 8; nj++)
                    mma16816(acc[mi][nj], ah[mi], bb[nj]);
            #pragma unroll
            for (int mi = 0; mi < 2; mi++)
                #pragma unroll
                for (int nj = 0; nj < 8; nj++)
                    mma16816(acc[mi][nj], al[mi], bb[nj]);
            #pragma unroll
            for (int p = 0; p < 4; p++){
                int u = wn * 8 + p * 2 + (lane >> 4);
                uint32_t off = bk * 256 + (((uint32_t)(u ^ (bk & 7))) << 4);
                ldsm4t(aBl + off, bb[2*p], bb[2*p+1]);
            }
            #pragma unroll
            for (int mi = 0; mi < 2; mi++)
                #pragma unroll
                for (int nj = 0; nj < 8; nj++)
                    mma16816(acc[mi][nj], ah[mi], bb[nj]);
        }

        if (kc + 2 < NK) fill(kc + 2, (kc + 2) % STAGES);
        else CP_COMMIT();
    }

    // ---- epilogue: acc -> smem (padded) -> global
    __syncthreads();
    float* sf = (float*)smem;
    {
        const int mrow = wm * 32 + (lane >> 2);
        const int ncol = wn * 64 + (lane & 3) * 2;
        #pragma unroll
        for (int mi = 0; mi < 2; mi++)
            #pragma unroll
            for (int nj = 0; nj < 8; nj++){
                int m = mrow + mi * 16, n = ncol + nj * 8;
                *(float2*)&sf[(size_t)m * 132 + n]       = make_float2(acc[mi][nj][0], acc[mi][nj][1]);
                *(float2*)&sf[(size_t)(m + 8) * 132 + n] = make_float2(acc[mi][nj][2], acc[mi][nj][3]);
            }
    }
    __syncthreads();

    for (int i = tid; i < BM * (BN / 4); i += 256){
        int r = i >> 5, c = (i & 31) * 4;
        float4 v = *(float4*)&sf[(size_t)r * 132 + c];
        float bm = biasM ? __ldg(biasM + row0 + r) : 0.f;
        float vv[4] = { v.x, v.y, v.z, v.w };
        #pragma unroll
        for (int j = 0; j < 4; j++){
            float t = vv[j] + bm + (biasN ? __ldg(biasN + col0 + c + j) : 0.f);
            if (EPI == 1) t = siluf(t);
            else if (EPI == 2) t = softplusf(t);
            vv[j] = t;
        }
        size_t o = (size_t)(row0 + r) * N + col0 + c;
        if (C) *(float4*)(C + o) = make_float4(vv[0], vv[1], vv[2], vv[3]);
        if (SPLIT){
            bf16 hh[4], ll[4];
            #pragma unroll
            for (int j = 0; j < 4; j++) splitf(vv[j], hh[j], ll[j]);
            *(uint2*)(Ch + o) = *(uint2*)hh;
            *(uint2*)(Cl + o) = *(uint2*)ll;
        }
    }
}

// ------------------------- aux kernels -------------------------
__global__ void k_embed(const int* __restrict__ ids, const float* __restrict__ emb)
{
    int row = blockIdx.x;
    int id  = ids[row];
    const float* src = emb + (size_t)id * DMODEL;
    float s = 0.f, ss = 0.f;
    for (int d = threadIdx.x; d < DMODEL; d += blockDim.x){
        float v = __ldg(src + d);
        g_x[(size_t)row * DMODEL + d] = v;
        s += v; ss += v * v;
    }
    __shared__ float sh[64];
    int lane = threadIdx.x & 31, w = threadIdx.x >> 5;
    #pragma unroll
    for (int o = 16; o; o >>= 1){
        s  += __shfl_down_sync(0xffffffffu, s,  o);
        ss += __shfl_down_sync(0xffffffffu, ss, o);
    }
    if (!lane){ sh[w] = s; sh[32 + w] = ss; }
    __syncthreads();
    if (threadIdx.x == 0){
        float S = 0.f, SS = 0.f;
        int nw = blockDim.x >> 5;
        for (int i = 0; i < nw; i++){ S += sh[i]; SS += sh[32 + i]; }
        g_rowsum[row] = S; g_rowsq[row] = SS;
    }
}

__global__ void k_samplestats()
{
    int b = blockIdx.x;
    float s = 0.f, ss = 0.f;
    for (int r = threadIdx.x; r < LSEQ; r += blockDim.x){
        s += g_rowsum[b * LSEQ + r]; ss += g_rowsq[b * LSEQ + r];
    }
    __shared__ float sh[64];
    int lane = threadIdx.x & 31, w = threadIdx.x >> 5;
    #pragma unroll
    for (int o = 16; o; o >>= 1){
        s  += __shfl_down_sync(0xffffffffu, s,  o);
        ss += __shfl_down_sync(0xffffffffu, ss, o);
    }
    if (!lane){ sh[w] = s; sh[32 + w] = ss; }
    __syncthreads();
    if (threadIdx.x == 0){
        float S = 0.f, SS = 0.f;
        int nw = blockDim.x >> 5;
        for (int i = 0; i < nw; i++){ S += sh[i]; SS += sh[32 + i]; }
        float inv = 1.f / ((float)LSEQ * (float)DMODEL);
        float mu  = S * inv;
        float var = SS * inv - mu * mu;
        g_mu[b]   = mu;
        g_rsig[b] = rsqrtf(var + 1e-5f);
    }
}

__global__ void k_norm(const float* __restrict__ rms_w)
{
    int row = blockIdx.x;
    int b = row >> 10;
    float mu = g_mu[b], rs = g_rsig[b];
    float msq = rs * rs * (g_rowsq[row] - 2.f * mu * g_rowsum[row] + (float)DMODEL * mu * mu) / (float)DMODEL;
    float a = rs * rsqrtf(msq + 1e-5f);
    const float* xr = g_x + (size_t)row * DMODEL;
    for (int d = threadIdx.x; d < DMODEL; d += blockDim.x){
        float v = (xr[d] - mu) * a * rms_w[d];
        bf16 h, l; splitf(v, h, l);
        g_xnP_h[(size_t)row * DMODEL + d] = h;
        g_xnP_l[(size_t)row * DMODEL + d] = l;
    }
}

// split with column offset into a wider destination: dst[k][off+c] = W[k][c]
__global__ void k_wsplit2(const float* __restrict__ W, bf16* __restrict__ Wh, bf16* __restrict__ Wl,
                          int Nsrc, int Ndst, int off)
{
    size_t i4 = (size_t)blockIdx.x * blockDim.x + threadIdx.x;
    int nq = Nsrc / 4;
    int k  = (int)(i4 / nq);
    int c  = (int)(i4 % nq) * 4;
    float4 v = *(const float4*)(W + (size_t)k * Nsrc + c);
    bf16 hh[4], ll[4];
    splitf(v.x, hh[0], ll[0]); splitf(v.y, hh[1], ll[1]);
    splitf(v.z, hh[2], ll[2]); splitf(v.w, hh[3], ll[3]);
    size_t o = (size_t)k * Ndst + off + c;
    *(uint2*)(Wh + o) = *(uint2*)hh;
    *(uint2*)(Wl + o) = *(uint2*)ll;
}

__global__ void k_bcat(const float* __restrict__ b_in, const float* __restrict__ b_D)
{
    int i = blockIdx.x * 256 + threadIdx.x;
    g_b15[i] = (i < D2V) ? b_in[i] : b_D[i - D2V];
}

// conv A repack: cA[o][k*1024+i] = conv_w[o][3i+k]
__global__ void k_convA(const float* __restrict__ cw)
{
    int o = blockIdx.y;
    int i = blockIdx.x * 256 + threadIdx.x;
    #pragma unroll
    for (int k = 0; k < 3; k++){
        float v = cw[(size_t)o * K3 + 3 * i + k];
        bf16 h, l; splitf(v, h, l);
        size_t off = (size_t)o * K3 + k * 1024 + i;
        g_cA_h[off] = h; g_cA_l[off] = l;
    }
}

// conv B gather (vectorized): cB[b][k*1024+i][t] = xp[b][i][t+k-1]; xp = g_xpr cols 0-1535
__global__ void k_convB()
{
    int t4 = threadIdx.x * 4;
    int i  = blockIdx.x;
    int zk = blockIdx.y;
    int b = zk / 3, k = zk % 3;
    const float* src = g_xpr + ((size_t)(b * LSEQ) + i) * N2X;
    bf16 hh[4], ll[4];
    #pragma unroll
    for (int j = 0; j < 4; j++){
        int tt = t4 + j + k - 1;
        float v = (tt >= 0 && tt < D2V) ? src[tt] : 0.f;
        splitf(v, hh[j], ll[j]);
    }
    size_t o = (size_t)b * K3 * D2V + (size_t)(k * 1024 + i) * D2V + t4;
    *(uint2*)(g_cB_h + o) = *(uint2*)hh;
    *(uint2*)(g_cB_l + o) = *(uint2*)ll;
}

__global__ void k_bcs(const float* __restrict__ w2, const float* __restrict__ b2,
                      const float* __restrict__ w3, const float* __restrict__ b3)
{
    int row = blockIdx.x;
    const float* xr = g_xco + (size_t)row * D2V;
    float ab[NSTATE], ac[NSTATE];
    #pragma unroll
    for (int n = 0; n < NSTATE; n++){ ab[n] = 0.f; ac[n] = 0.f; }
    for (int k = threadIdx.x; k < D2V; k += blockDim.x){
        float xv = xr[k];
        const float4* q2 = (const float4*)(w2 + (size_t)k * NSTATE);
        const float4* q3 = (const float4*)(w3 + (size_t)k * NSTATE);
        #pragma unroll
        for (int q = 0; q < 4; q++){
            float4 a = q2[q], c = q3[q];
            ab[4*q+0] += xv*a.x; ab[4*q+1] += xv*a.y; ab[4*q+2] += xv*a.z; ab[4*q+3] += xv*a.w;
            ac[4*q+0] += xv*c.x; ac[4*q+1] += xv*c.y; ac[4*q+2] += xv*c.z; ac[4*q+3] += xv*c.w;
        }
    }
    __shared__ float shb[NSTATE], shc[NSTATE];
    if (threadIdx.x < NSTATE){ shb[threadIdx.x] = 0.f; shc[threadIdx.x] = 0.f; }
    __syncthreads();
    int lane = threadIdx.x & 31;
    #pragma unroll
    for (int n = 0; n < NSTATE; n++){
        float vb = ab[n], vc = ac[n];
        #pragma unroll
        for (int o = 16; o; o >>= 1){
            vb += __shfl_down_sync(0xffffffffu, vb, o);
            vc += __shfl_down_sync(0xffffffffu, vc, o);
        }
        if (lane == 0){ atomicAdd(&shb[n], vb); atomicAdd(&shc[n], vc); }
    }
    __syncthreads();
    if (threadIdx.x == 0){
        float s = 0.f;
        #pragma unroll
        for (int n = 0; n < NSTATE; n++) s += (shb[n] + b2[n]) * (shc[n] + b3[n]);
        g_s[row] = s;
    }
}

// prod = silu(xco*delta*s) * silu(xres_raw);  xres_raw = g_xpr cols 1536-3071
__global__ void k_prod()
{
    size_t i4 = (size_t)blockIdx.x * blockDim.x + threadIdx.x;
    int row = (int)(i4 / (D2V / 4));
    int c4  = (int)(i4 % (D2V / 4));
    float sv = g_s[row];
    float4 xo = ((const float4*)g_xco)[i4];
    float4 dl = ((const float4*)g_dl )[i4];
    float4 xr = *(const float4*)(g_xpr + (size_t)row * N2X + D2V + c4 * 4);
    float r0 = siluf(xo.x*dl.x*sv) * siluf(xr.x);
    float r1 = siluf(xo.y*dl.y*sv) * siluf(xr.y);
    float r2 = siluf(xo.z*dl.z*sv) * siluf(xr.z);
    float r3 = siluf(xo.w*dl.w*sv) * siluf(xr.w);
    bf16 hh[4], ll[4];
    splitf(r0, hh[0], ll[0]); splitf(r1, hh[1], ll[1]);
    splitf(r2, hh[2], ll[2]); splitf(r3, hh[3], ll[3]);
    *(uint2*)(g_prP_h + i4*4) = *(uint2*)hh;
    *(uint2*)(g_prP_l + i4*4) = *(uint2*)ll;
}

__global__ void k_maxpool(const float* __restrict__ out, float* __restrict__ pooled)
{
    int b = blockIdx.y;
    int d = blockIdx.x * blockDim.x + threadIdx.x;
    if (d >= DMODEL) return;
    const float* p = out + (size_t)b * LSEQ * DMODEL + d;
    float m = -FLT_MAX;
    for (int l = 0; l < LSEQ; l++) m = fmaxf(m, p[(size_t)l * DMODEL]);
    pooled[b * DMODEL + d] = m;
}

// ------------------------- launch -------------------------
extern "C" void kernel_launch(void* const* d_in, const int* in_sizes, int n_in,
                              void* d_out, int out_size)
{
    const int*   ids    = (const int*)  d_in[0];
    const float* emb    = (const float*)d_in[1];
    const float* rms_w  = (const float*)d_in[2];
    const float* W_in   = (const float*)d_in[3];
    const float* b_in   = (const float*)d_in[4];
    const float* conv_w = (const float*)d_in[5];
    const float* conv_b = (const float*)d_in[6];
    const float* W_cl   = (const float*)d_in[7];
    const float* b_cl   = (const float*)d_in[8];
    const float* fc1_w  = (const float*)d_in[9];
    const float* fc1_b  = (const float*)d_in[10];
    const float* fc2_w  = (const float*)d_in[11];
    const float* fc2_b  = (const float*)d_in[12];
    const float* fc3_w  = (const float*)d_in[13];
    const float* fc3_b  = (const float*)d_in[14];
    const float* W_D    = (const float*)d_in[16];
    const float* b_D    = (const float*)d_in[17];
    const float* W_out  = (const float*)d_in[18];
    const float* b_out  = (const float*)d_in[19];
    float* out = (float*)d_out;

    cudaFuncSetAttribute(k_tc<0,false>, cudaFuncAttributeMaxDynamicSharedMemorySize, SMEM_DYN);
    cudaFuncSetAttribute(k_tc<0,true >, cudaFuncAttributeMaxDynamicSharedMemorySize, SMEM_DYN);
    cudaFuncSetAttribute(k_tc<1,true >, cudaFuncAttributeMaxDynamicSharedMemorySize, SMEM_DYN);
    cudaFuncSetAttribute(k_tc<2,false>, cudaFuncAttributeMaxDynamicSharedMemorySize, SMEM_DYN);

    bf16 *xnh, *xnl, *xcah, *xcal, *xcoh, *xcol, *prh, *prl;
    bf16 *w15h, *w15l, *wclh, *wcll, *f1h, *f1l, *woh, *wol;
    bf16 *cah, *cal, *cbh, *cbl;
    float *pxpr, *pxco, *pdl, *pb15;
    cudaGetSymbolAddress((void**)&xnh,  g_xnP_h);  cudaGetSymbolAddress((void**)&xnl,  g_xnP_l);
    cudaGetSymbolAddress((void**)&xcah, g_xcaP_h); cudaGetSymbolAddress((void**)&xcal, g_xcaP_l);
    cudaGetSymbolAddress((void**)&xcoh, g_xcoP_h); cudaGetSymbolAddress((void**)&xcol, g_xcoP_l);
    cudaGetSymbolAddress((void**)&prh,  g_prP_h);  cudaGetSymbolAddress((void**)&prl,  g_prP_l);
    cudaGetSymbolAddress((void**)&w15h, g_W15_h);  cudaGetSymbolAddress((void**)&w15l, g_W15_l);
    cudaGetSymbolAddress((void**)&wclh, g_WclS_h); cudaGetSymbolAddress((void**)&wcll, g_WclS_l);
    cudaGetSymbolAddress((void**)&f1h,  g_fc1S_h); cudaGetSymbolAddress((void**)&f1l,  g_fc1S_l);
    cudaGetSymbolAddress((void**)&woh,  g_WoS_h);  cudaGetSymbolAddress((void**)&wol,  g_WoS_l);
    cudaGetSymbolAddress((void**)&cah,  g_cA_h);   cudaGetSymbolAddress((void**)&cal,  g_cA_l);
    cudaGetSymbolAddress((void**)&cbh,  g_cB_h);   cudaGetSymbolAddress((void**)&cbl,  g_cB_l);
    cudaGetSymbolAddress((void**)&pxpr, g_xpr);
    cudaGetSymbolAddress((void**)&pxco, g_xco);
    cudaGetSymbolAddress((void**)&pdl,  g_dl);
    cudaGetSymbolAddress((void**)&pb15, g_b15);

    // weight packs
    k_wsplit2<<<(DMODEL*D2V/4)/256, 256>>>(W_in,  w15h, w15l, D2V, N2X, 0);
    k_wsplit2<<<(DMODEL*D2V/4)/256, 256>>>(W_D,   w15h, w15l, D2V, N2X, D2V);
    k_wsplit2<<<(D2V*D2V/4)/256,    256>>>(W_cl,  wclh, wcll, D2V, D2V, 0);
    k_wsplit2<<<(D2V*D2V/4)/256,    256>>>(fc1_w, f1h,  f1l,  D2V, D2V, 0);
    k_wsplit2<<<(D2V*DMODEL/4)/256, 256>>>(W_out, woh,  wol,  DMODEL, DMODEL, 0);
    k_bcat<<<N2X/256, 256>>>(b_in, b_D);
    k_convA<<<dim3(LSEQ/256, LSEQ), 256>>>(conv_w);

    // embed + norms
    k_embed<<<ROWS, 256>>>(ids, emb);
    k_samplestats<<<BATCH, 256>>>();
    k_norm<<<ROWS, 256>>>(rms_w);

    // GEMM1+5 fused: [xp | xres_raw] = xn @ [W_in | W_D] + [b_in | b_D]
    k_tc<0,false><<<dim3(N2X/BN, ROWS/BM, 1), 256, SMEM_DYN>>>(
        xnh, xnl, w15h, w15l, pb15, nullptr, pxpr, nullptr, nullptr,
        DMODEL, N2X, 0, 0, 0);

    // conv operand gather (vectorized, k-major)
    k_convB<<<dim3(LSEQ, 3*BATCH), 384>>>();

    // GEMM2 (conv): xca = silu(cA @ cB + conv_b[row]), split-only output
    k_tc<1,true><<<dim3(D2V/BN, LSEQ/BM, BATCH), 256, SMEM_DYN>>>(
        cah, cal, cbh, cbl, nullptr, conv_b, nullptr, xcah, xcal,
        K3, D2V, 0, (long)K3*D2V, (long)LSEQ*D2V);

    // GEMM3: xco = xca @ W_cl + b_cl (float + split)
    k_tc<0,true><<<dim3(D2V/BN, ROWS/BM, 1), 256, SMEM_DYN>>>(
        xcah, xcal, wclh, wcll, b_cl, nullptr, pxco, xcoh, xcol,
        D2V, D2V, 0, 0, 0);

    // GEMM4: delta = softplus(xco @ fc1 + b1)
    k_tc<2,false><<<dim3(D2V/BN, ROWS/BM, 1), 256, SMEM_DYN>>>(
        xcoh, xcol, f1h, f1l, fc1_b, nullptr, pdl, nullptr, nullptr,
        D2V, D2V, 0, 0, 0);

    // s[row] = sum_n Bm*Cm
    k_bcs<<<ROWS, 256>>>(fc2_w, fc2_b, fc3_w, fc3_b);

    // prod = silu(xco*delta*s) * silu(xres_raw)  (split for GEMM6)
    k_prod<<<(ROWS * D2V / 4) / 256, 256>>>();

    // GEMM6: out = prod @ W_out + b_out
    k_tc<0,false><<<dim3(DMODEL/BN, ROWS/BM, 1), 256, SMEM_DYN>>>(
        prh, prl, woh, wol, b_out, nullptr, out, nullptr, nullptr,
        D2V, DMODEL, 0, 0, 0);

    if (out_size >= ROWS * DMODEL + BATCH * DMODEL)
        k_maxpool<<<dim3((DMODEL + 255) / 256, BATCH), 256>>>(out, out + (size_t)ROWS * DMODEL);
}

// round 7
// speedup vs baseline: 1.9001x; 1.1259x over previous
#include <cuda_runtime.h>
#include <cuda_bf16.h>
#include <math.h>
#include <float.h>
#include <stdint.h>

#define BATCH 8
#define LSEQ 1024
#define DMODEL 768
#define D2V 1536
#define N2X 3072
#define N17 1792
#define NSTATE 16
#define ROWS (BATCH*LSEQ)
#define K3 (3*LSEQ)

// narrow kernel (128x128, R4-proven) for GEMM6
#define BM 128
#define BN 128
#define NSTAGES 3
#define NSTAGE_BYTES 65536u
#define NSMEM (NSTAGES*NSTAGE_BYTES)

// wide kernel (128x256)
#define WSTAGE 98304u
#define WOFF_AL 16384u
#define WOFF_BH 32768u
#define WOFF_BL 65536u
#define WSMEM (2u*WSTAGE)

typedef __nv_bfloat16 bf16;

// ------------------------- device scratch -------------------------
__device__ float g_x   [ROWS*DMODEL];
__device__ float g_xpr [(size_t)ROWS*N2X];   // [xp | xres_raw]
__device__ float g_xco [ROWS*D2V];
__device__ float g_dl  [(size_t)ROWS*N17];   // [softplus(fc1) | Bm | Cm | pad]
__device__ float g_rowsum[ROWS];
__device__ float g_rowsq [ROWS];
__device__ float g_mu  [BATCH];
__device__ float g_rsig[BATCH];
__device__ float g_s   [ROWS];
__device__ float g_b15 [N2X];
__device__ float g_b17 [N17];

__device__ bf16 g_xnP_h [ROWS*DMODEL], g_xnP_l [ROWS*DMODEL];
__device__ bf16 g_xcaP_h[ROWS*D2V],    g_xcaP_l[ROWS*D2V];
__device__ bf16 g_xcoP_h[ROWS*D2V],    g_xcoP_l[ROWS*D2V];
__device__ bf16 g_prP_h [ROWS*D2V],    g_prP_l [ROWS*D2V];
__device__ bf16 g_W15_h [DMODEL*N2X],  g_W15_l [DMODEL*N2X];
__device__ bf16 g_WclS_h[D2V*D2V],     g_WclS_l[D2V*D2V];
__device__ bf16 g_f17_h [(size_t)D2V*N17], g_f17_l [(size_t)D2V*N17]; // zero-init cols 1568+
__device__ bf16 g_WoS_h [D2V*DMODEL],  g_WoS_l [D2V*DMODEL];
__device__ bf16 g_cA_h  [LSEQ*K3],     g_cA_l  [LSEQ*K3];
__device__ bf16 g_cB_h  [(size_t)BATCH*K3*D2V];
__device__ bf16 g_cB_l  [(size_t)BATCH*K3*D2V];

// ------------------------- helpers -------------------------
__device__ __forceinline__ float siluf(float v){ return v / (1.f + expf(-v)); }
__device__ __forceinline__ float softplusf(float v){ return (v > 20.f) ? v : log1pf(expf(v)); }

__device__ __forceinline__ uint32_t smem_u32(const void* p){
    uint32_t a;
    asm("{ .reg .u64 t; cvta.to.shared.u64 t, %1; cvt.u32.u64 %0, t; }" : "=r"(a) : "l"(p));
    return a;
}
__device__ __forceinline__ void cpa16(uint32_t dst, const void* src){
    asm volatile("cp.async.cg.shared.global [%0], [%1], 16;" :: "r"(dst), "l"(src) : "memory");
}
#define CP_COMMIT() asm volatile("cp.async.commit_group;" ::: "memory")
#define CP_WAIT(n)  asm volatile("cp.async.wait_group %0;" :: "n"(n) : "memory")

__device__ __forceinline__ void ldsm4(uint32_t addr, uint32_t* r){
    asm volatile("ldmatrix.sync.aligned.m8n8.x4.shared.b16 {%0,%1,%2,%3}, [%4];"
        : "=r"(r[0]), "=r"(r[1]), "=r"(r[2]), "=r"(r[3]) : "r"(addr));
}
__device__ __forceinline__ void ldsm4t(uint32_t addr, uint32_t* r0, uint32_t* r1){
    asm volatile("ldmatrix.sync.aligned.m8n8.x4.trans.shared.b16 {%0,%1,%2,%3}, [%4];"
        : "=r"(r0[0]), "=r"(r0[1]), "=r"(r1[0]), "=r"(r1[1]) : "r"(addr));
}
__device__ __forceinline__ void mma16816(float* d, const uint32_t* a, const uint32_t* b){
    asm volatile("mma.sync.aligned.m16n8k16.row.col.f32.bf16.bf16.f32 "
        "{%0,%1,%2,%3}, {%4,%5,%6,%7}, {%8,%9}, {%0,%1,%2,%3};"
        : "+f"(d[0]), "+f"(d[1]), "+f"(d[2]), "+f"(d[3])
        : "r"(a[0]), "r"(a[1]), "r"(a[2]), "r"(a[3]), "r"(b[0]), "r"(b[1]));
}
__device__ __forceinline__ void splitf(float v, bf16& h, bf16& l){
    h = __float2bfloat16(v);
    l = __float2bfloat16(v - __bfloat162float(h));
}

// ------------------------- WIDE HMMA GEMM 128x256 -------------------------
// C[M,N] = EPI(A@B + biasN + biasM). EPI: 0 none, 1 silu, 2 softplus, 3 softplus iff col<D2V.
template<int EPI, bool SPLIT>
__global__ void __launch_bounds__(256, 1) k_tcW(
    const bf16* __restrict__ Ah, const bf16* __restrict__ Al,
    const bf16* __restrict__ Bh, const bf16* __restrict__ Bl,
    const float* __restrict__ biasN, const float* __restrict__ biasM,
    float* __restrict__ C, bf16* __restrict__ Ch, bf16* __restrict__ Cl,
    int K, int N, long sA, long sB, long sC)
{
    extern __shared__ char smem[];
    const int tid  = threadIdx.x;
    const int wid  = tid >> 5, lane = tid & 31;
    const int wm   = wid & 1,  wn = wid >> 1;     // warp tile 64x64: rows wm*64, cols wn*64
    const int row0 = blockIdx.y * 128;
    const int col0 = blockIdx.x * 256;
    Ah += (size_t)blockIdx.z * sA;  Al += (size_t)blockIdx.z * sA;
    Bh += (size_t)blockIdx.z * sB;  Bl += (size_t)blockIdx.z * sB;
    if (C) C += (size_t)blockIdx.z * sC;
    if (SPLIT){ Ch += (size_t)blockIdx.z * sC; Cl += (size_t)blockIdx.z * sC; }
    const int NK = K >> 6;
    const uint32_t sbase = smem_u32(smem);

    float acc[4][8][4];
    #pragma unroll
    for (int mi = 0; mi < 4; mi++)
        #pragma unroll
        for (int nj = 0; nj < 8; nj++)
            #pragma unroll
            for (int q = 0; q < 4; q++) acc[mi][nj][q] = 0.f;

    auto fill = [&](int kc, int s){
        uint32_t st = sbase + (uint32_t)s * WSTAGE;
        const bf16* ap[2] = { Ah, Al };
        #pragma unroll
        for (int arr = 0; arr < 2; arr++){
            uint32_t base = st + arr * WOFF_AL;
            #pragma unroll
            for (int it = 0; it < 4; it++){
                int id = tid + it * 256;
                int r = id >> 3, u = id & 7;
                cpa16(base + r * 128 + (((uint32_t)(u ^ (r & 7))) << 4),
                      ap[arr] + (size_t)(row0 + r) * K + kc * 64 + u * 8);
            }
        }
        const bf16* bp[2] = { Bh, Bl };
        #pragma unroll
        for (int arr = 0; arr < 2; arr++){
            uint32_t base = st + WOFF_BH + arr * (WOFF_BL - WOFF_BH);
            #pragma unroll
            for (int it = 0; it < 8; it++){
                int id = tid + it * 256;
                int k = id >> 5, u = id & 31;
                cpa16(base + k * 512 + (((uint32_t)(u ^ (k & 7))) << 4),
                      bp[arr] + (size_t)(kc * 64 + k) * N + col0 + u * 8);
            }
        }
        CP_COMMIT();
    };

    fill(0, 0);
    fill(1, 1);

    for (int kc = 0; kc < NK; kc++){
        int s = kc & 1;
        CP_WAIT(1);
        __syncthreads();

        uint32_t aAh = sbase + (uint32_t)s * WSTAGE;
        uint32_t aAl = aAh + WOFF_AL;
        uint32_t aBh = aAh + WOFF_BH;
        uint32_t aBl = aAh + WOFF_BL;

        #pragma unroll
        for (int ks = 0; ks < 4; ks++){
            uint32_t ah[4][4], al[4][4];
            const int au = 2 * ks + (lane >> 4);
            #pragma unroll
            for (int mi = 0; mi < 4; mi++){
                int r = wm * 64 + mi * 16 + (lane & 15);
                uint32_t off = r * 128 + (((uint32_t)(au ^ (r & 7))) << 4);
                ldsm4(aAh + off, ah[mi]);
                ldsm4(aAl + off, al[mi]);
            }
            const int bk = ks * 16 + (lane & 15);
            // B-hi: hh + lh passes
            #pragma unroll
            for (int p = 0; p < 4; p++){
                int u = wn * 8 + p * 2 + (lane >> 4);
                uint32_t off = bk * 512 + (((uint32_t)(u ^ (bk & 7))) << 4);
                uint32_t b0[2], b1[2];
                ldsm4t(aBh + off, b0, b1);
                #pragma unroll
                for (int mi = 0; mi < 4; mi++){
                    mma16816(acc[mi][2*p],   ah[mi], b0);
                    mma16816(acc[mi][2*p+1], ah[mi], b1);
                }
                #pragma unroll
                for (int mi = 0; mi < 4; mi++){
                    mma16816(acc[mi][2*p],   al[mi], b0);
                    mma16816(acc[mi][2*p+1], al[mi], b1);
                }
            }
            // B-lo: hl pass
            #pragma unroll
            for (int p = 0; p < 4; p++){
                int u = wn * 8 + p * 2 + (lane >> 4);
                uint32_t off = bk * 512 + (((uint32_t)(u ^ (bk & 7))) << 4);
                uint32_t b0[2], b1[2];
                ldsm4t(aBl + off, b0, b1);
                #pragma unroll
                for (int mi = 0; mi < 4; mi++){
                    mma16816(acc[mi][2*p],   ah[mi], b0);
                    mma16816(acc[mi][2*p+1], ah[mi], b1);
                }
            }
        }

        __syncthreads();
        if (kc + 2 < NK) fill(kc + 2, s);
        else CP_COMMIT();
    }

    CP_WAIT(0);
    __syncthreads();

    // ---- epilogue: acc -> smem (260-pitch) -> global
    float* sf = (float*)smem;
    {
        const int rlo = lane >> 2;
        const int ncl = (lane & 3) * 2;
        #pragma unroll
        for (int mi = 0; mi < 4; mi++)
            #pragma unroll
            for (int nj = 0; nj < 8; nj++){
                int m = wm * 64 + mi * 16 + rlo;
                int n = wn * 64 + nj * 8 + ncl;
                *(float2*)&sf[(size_t)m * 260 + n]       = make_float2(acc[mi][nj][0], acc[mi][nj][1]);
                *(float2*)&sf[(size_t)(m + 8) * 260 + n] = make_float2(acc[mi][nj][2], acc[mi][nj][3]);
            }
    }
    __syncthreads();

    for (int i = tid; i < 128 * 64; i += 256){
        int r = i >> 6, c = (i & 63) * 4;
        float4 v = *(float4*)&sf[(size_t)r * 260 + c];
        float bm = biasM ? __ldg(biasM + row0 + r) : 0.f;
        float vv[4] = { v.x, v.y, v.z, v.w };
        #pragma unroll
        for (int j = 0; j < 4; j++){
            float t = vv[j] + bm + (biasN ? __ldg(biasN + col0 + c + j) : 0.f);
            if (EPI == 1) t = siluf(t);
            else if (EPI == 2) t = softplusf(t);
            else if (EPI == 3){ if (col0 + c + j < D2V) t = softplusf(t); }
            vv[j] = t;
        }
        size_t o = (size_t)(row0 + r) * N + col0 + c;
        if (C) *(float4*)(C + o) = make_float4(vv[0], vv[1], vv[2], vv[3]);
        if (SPLIT){
            bf16 hh[4], ll[4];
            #pragma unroll
            for (int j = 0; j < 4; j++) splitf(vv[j], hh[j], ll[j]);
            *(uint2*)(Ch + o) = *(uint2*)hh;
            *(uint2*)(Cl + o) = *(uint2*)ll;
        }
    }
}

// ------------------------- NARROW HMMA GEMM 128x128 (R4-proven, GEMM6) ----
__global__ void __launch_bounds__(256, 1) k_tcN(
    const bf16* __restrict__ Ah, const bf16* __restrict__ Al,
    const bf16* __restrict__ Bh, const bf16* __restrict__ Bl,
    const float* __restrict__ biasN,
    float* __restrict__ C, int K, int N)
{
    extern __shared__ char smem[];
    const int tid  = threadIdx.x;
    const int wid  = tid >> 5, lane = tid & 31;
    const int wm   = wid & 3,  wn = wid >> 2;
    const int row0 = blockIdx.y * BM;
    const int col0 = blockIdx.x * BN;
    const int NK = K >> 6;
    const uint32_t sbase = smem_u32(smem);

    float acc[2][8][4];
    #pragma unroll
    for (int mi = 0; mi < 2; mi++)
        #pragma unroll
        for (int nj = 0; nj < 8; nj++)
            #pragma unroll
            for (int q = 0; q < 4; q++) acc[mi][nj][q] = 0.f;

    auto fill = [&](int kc, int s){
        uint32_t st = sbase + (uint32_t)s * NSTAGE_BYTES;
        const bf16* ap[2] = { Ah, Al };
        #pragma unroll
        for (int arr = 0; arr < 2; arr++){
            uint32_t base = st + arr * 16384u;
            #pragma unroll
            for (int it = 0; it < 4; it++){
                int id = tid + it * 256;
                int r = id >> 3, u = id & 7;
                cpa16(base + r * 128 + (((uint32_t)(u ^ (r & 7))) << 4),
                      ap[arr] + (size_t)(row0 + r) * K + kc * 64 + u * 8);
            }
        }
        const bf16* bp[2] = { Bh, Bl };
        #pragma unroll
        for (int arr = 0; arr < 2; arr++){
            uint32_t base = st + 32768u + arr * 16384u;
            #pragma unroll
            for (int it = 0; it < 4; it++){
                int id = tid + it * 256;
                int k = id >> 4, u = id & 15;
                cpa16(base + k * 256 + (((uint32_t)(u ^ (k & 7))) << 4),
                      bp[arr] + (size_t)(kc * 64 + k) * N + col0 + u * 8);
            }
        }
        CP_COMMIT();
    };

    fill(0, 0);
    if (NK > 1) fill(1, 1); else CP_COMMIT();

    for (int kc = 0; kc < NK; kc++){
        int s = kc % NSTAGES;
        CP_WAIT(1);
        __syncthreads();

        uint32_t aAh = sbase + (uint32_t)s * NSTAGE_BYTES;
        uint32_t aAl = aAh + 16384u;
        uint32_t aBh = aAh + 32768u;
        uint32_t aBl = aAh + 49152u;

        #pragma unroll
        for (int ks = 0; ks < 4; ks++){
            uint32_t ah[2][4], al[2][4], bb[8][2];
            const int arow = wm * 32 + (lane & 15);
            const int au   = 2 * ks + (lane >> 4);
            #pragma unroll
            for (int mi = 0; mi < 2; mi++){
                int r = arow + mi * 16;
                uint32_t off = r * 128 + (((uint32_t)(au ^ (r & 7))) << 4);
                ldsm4(aAh + off, ah[mi]);
                ldsm4(aAl + off, al[mi]);
            }
            const int bk = ks * 16 + (lane & 15);
            #pragma unroll
            for (int p = 0; p < 4; p++){
                int u = wn * 8 + p * 2 + (lane >> 4);
                uint32_t off = bk * 256 + (((uint32_t)(u ^ (bk & 7))) << 4);
                ldsm4t(aBh + off, bb[2*p], bb[2*p+1]);
            }
            #pragma unroll
            for (int mi = 0; mi < 2; mi++)
                #pragma unroll
                for (int nj = 0; nj < 8; nj++)
                    mma16816(acc[mi][nj], ah[mi], bb[nj]);
            #pragma unroll
            for (int mi = 0; mi < 2; mi++)
                #pragma unroll
                for (int nj = 0; nj < 8; nj++)
                    mma16816(acc[mi][nj], al[mi], bb[nj]);
            #pragma unroll
            for (int p = 0; p < 4; p++){
                int u = wn * 8 + p * 2 + (lane >> 4);
                uint32_t off = bk * 256 + (((uint32_t)(u ^ (bk & 7))) << 4);
                ldsm4t(aBl + off, bb[2*p], bb[2*p+1]);
            }
            #pragma unroll
            for (int mi = 0; mi < 2; mi++)
                #pragma unroll
                for (int nj = 0; nj < 8; nj++)
                    mma16816(acc[mi][nj], ah[mi], bb[nj]);
        }

        if (kc + 2 < NK) fill(kc + 2, (kc + 2) % NSTAGES);
        else CP_COMMIT();
    }

    __syncthreads();
    float* sf = (float*)smem;
    {
        const int mrow = wm * 32 + (lane >> 2);
        const int ncol = wn * 64 + (lane & 3) * 2;
        #pragma unroll
        for (int mi = 0; mi < 2; mi++)
            #pragma unroll
            for (int nj = 0; nj < 8; nj++){
                int m = mrow + mi * 16, n = ncol + nj * 8;
                *(float2*)&sf[(size_t)m * 132 + n]       = make_float2(acc[mi][nj][0], acc[mi][nj][1]);
                *(float2*)&sf[(size_t)(m + 8) * 132 + n] = make_float2(acc[mi][nj][2], acc[mi][nj][3]);
            }
    }
    __syncthreads();

    for (int i = tid; i < BM * (BN / 4); i += 256){
        int r = i >> 5, c = (i & 31) * 4;
        float4 v = *(float4*)&sf[(size_t)r * 132 + c];
        float vv[4] = { v.x, v.y, v.z, v.w };
        #pragma unroll
        for (int j = 0; j < 4; j++)
            vv[j] += (biasN ? __ldg(biasN + col0 + c + j) : 0.f);
        *(float4*)(C + (size_t)(row0 + r) * N + col0 + c) = make_float4(vv[0], vv[1], vv[2], vv[3]);
    }
}

// ------------------------- aux kernels -------------------------
__global__ void k_embed(const int* __restrict__ ids, const float* __restrict__ emb)
{
    int row = blockIdx.x;
    int id  = ids[row];
    const float* src = emb + (size_t)id * DMODEL;
    float s = 0.f, ss = 0.f;
    for (int d = threadIdx.x; d < DMODEL; d += blockDim.x){
        float v = __ldg(src + d);
        g_x[(size_t)row * DMODEL + d] = v;
        s += v; ss += v * v;
    }
    __shared__ float sh[64];
    int lane = threadIdx.x & 31, w = threadIdx.x >> 5;
    #pragma unroll
    for (int o = 16; o; o >>= 1){
        s  += __shfl_down_sync(0xffffffffu, s,  o);
        ss += __shfl_down_sync(0xffffffffu, ss, o);
    }
    if (!lane){ sh[w] = s; sh[32 + w] = ss; }
    __syncthreads();
    if (threadIdx.x == 0){
        float S = 0.f, SS = 0.f;
        int nw = blockDim.x >> 5;
        for (int i = 0; i < nw; i++){ S += sh[i]; SS += sh[32 + i]; }
        g_rowsum[row] = S; g_rowsq[row] = SS;
    }
}

__global__ void k_samplestats()
{
    int b = blockIdx.x;
    float s = 0.f, ss = 0.f;
    for (int r = threadIdx.x; r < LSEQ; r += blockDim.x){
        s += g_rowsum[b * LSEQ + r]; ss += g_rowsq[b * LSEQ + r];
    }
    __shared__ float sh[64];
    int lane = threadIdx.x & 31, w = threadIdx.x >> 5;
    #pragma unroll
    for (int o = 16; o; o >>= 1){
        s  += __shfl_down_sync(0xffffffffu, s,  o);
        ss += __shfl_down_sync(0xffffffffu, ss, o);
    }
    if (!lane){ sh[w] = s; sh[32 + w] = ss; }
    __syncthreads();
    if (threadIdx.x == 0){
        float S = 0.f, SS = 0.f;
        int nw = blockDim.x >> 5;
        for (int i = 0; i < nw; i++){ S += sh[i]; SS += sh[32 + i]; }
        float inv = 1.f / ((float)LSEQ * (float)DMODEL);
        float mu  = S * inv;
        float var = SS * inv - mu * mu;
        g_mu[b]   = mu;
        g_rsig[b] = rsqrtf(var + 1e-5f);
    }
}

__global__ void k_norm(const float* __restrict__ rms_w)
{
    int row = blockIdx.x;
    int b = row >> 10;
    float mu = g_mu[b], rs = g_rsig[b];
    float msq = rs * rs * (g_rowsq[row] - 2.f * mu * g_rowsum[row] + (float)DMODEL * mu * mu) / (float)DMODEL;
    float a = rs * rsqrtf(msq + 1e-5f);
    const float* xr = g_x + (size_t)row * DMODEL;
    for (int d = threadIdx.x; d < DMODEL; d += blockDim.x){
        float v = (xr[d] - mu) * a * rms_w[d];
        bf16 h, l; splitf(v, h, l);
        g_xnP_h[(size_t)row * DMODEL + d] = h;
        g_xnP_l[(size_t)row * DMODEL + d] = l;
    }
}

__global__ void k_wsplit2(const float* __restrict__ W, bf16* __restrict__ Wh, bf16* __restrict__ Wl,
                          int Nsrc, int Ndst, int off)
{
    size_t i4 = (size_t)blockIdx.x * blockDim.x + threadIdx.x;
    int nq = Nsrc / 4;
    int k  = (int)(i4 / nq);
    int c  = (int)(i4 % nq) * 4;
    float4 v = *(const float4*)(W + (size_t)k * Nsrc + c);
    bf16 hh[4], ll[4];
    splitf(v.x, hh[0], ll[0]); splitf(v.y, hh[1], ll[1]);
    splitf(v.z, hh[2], ll[2]); splitf(v.w, hh[3], ll[3]);
    size_t o = (size_t)k * Ndst + off + c;
    *(uint2*)(Wh + o) = *(uint2*)hh;
    *(uint2*)(Wl + o) = *(uint2*)ll;
}

__global__ void k_bcat(const float* __restrict__ b_in, const float* __restrict__ b_D)
{
    int i = blockIdx.x * 256 + threadIdx.x;
    g_b15[i] = (i < D2V) ? b_in[i] : b_D[i - D2V];
}

__global__ void k_bcat17(const float* __restrict__ b1, const float* __restrict__ b2,
                         const float* __restrict__ b3)
{
    int i = blockIdx.x * 256 + threadIdx.x;
    float v = 0.f;
    if (i < D2V) v = b1[i];
    else if (i < D2V + 16) v = b2[i - D2V];
    else if (i < D2V + 32) v = b3[i - D2V - 16];
    g_b17[i] = v;
}

__global__ void k_convA(const float* __restrict__ cw)
{
    int o = blockIdx.y;
    int i = blockIdx.x * 256 + threadIdx.x;
    #pragma unroll
    for (int k = 0; k < 3; k++){
        float v = cw[(size_t)o * K3 + 3 * i + k];
        bf16 h, l; splitf(v, h, l);
        size_t off = (size_t)o * K3 + k * 1024 + i;
        g_cA_h[off] = h; g_cA_l[off] = l;
    }
}

__global__ void k_convB()
{
    int t4 = threadIdx.x * 4;
    int i  = blockIdx.x;
    int zk = blockIdx.y;
    int b = zk / 3, k = zk % 3;
    const float* src = g_xpr + ((size_t)(b * LSEQ) + i) * N2X;
    bf16 hh[4], ll[4];
    #pragma unroll
    for (int j = 0; j < 4; j++){
        int tt = t4 + j + k - 1;
        float v = (tt >= 0 && tt < D2V) ? src[tt] : 0.f;
        splitf(v, hh[j], ll[j]);
    }
    size_t o = (size_t)b * K3 * D2V + (size_t)(k * 1024 + i) * D2V + t4;
    *(uint2*)(g_cB_h + o) = *(uint2*)hh;
    *(uint2*)(g_cB_l + o) = *(uint2*)ll;
}

// s[row] = sum_n (Bm_n)(Cm_n) from fused GEMM4 columns
__global__ void k_s()
{
    int row = blockIdx.x;
    int lane = threadIdx.x;
    float p = 0.f;
    if (lane < NSTATE){
        float bm = g_dl[(size_t)row * N17 + D2V + lane];
        float cm = g_dl[(size_t)row * N17 + D2V + NSTATE + lane];
        p = bm * cm;
    }
    #pragma unroll
    for (int o = 8; o; o >>= 1) p += __shfl_xor_sync(0xffffffffu, p, o);
    if (lane == 0) g_s[row] = p;
}

// prod = silu(xco*delta*s) * silu(xres_raw)
__global__ void k_prod()
{
    size_t i4 = (size_t)blockIdx.x * blockDim.x + threadIdx.x;
    int row = (int)(i4 / (D2V / 4));
    int c4  = (int)(i4 % (D2V / 4));
    float sv = g_s[row];
    float4 xo = ((const float4*)g_xco)[i4];
    float4 dl = *(const float4*)(g_dl + (size_t)row * N17 + c4 * 4);
    float4 xr = *(const float4*)(g_xpr + (size_t)row * N2X + D2V + c4 * 4);
    float r0 = siluf(xo.x*dl.x*sv) * siluf(xr.x);
    float r1 = siluf(xo.y*dl.y*sv) * siluf(xr.y);
    float r2 = siluf(xo.z*dl.z*sv) * siluf(xr.z);
    float r3 = siluf(xo.w*dl.w*sv) * siluf(xr.w);
    bf16 hh[4], ll[4];
    splitf(r0, hh[0], ll[0]); splitf(r1, hh[1], ll[1]);
    splitf(r2, hh[2], ll[2]); splitf(r3, hh[3], ll[3]);
    *(uint2*)(g_prP_h + i4*4) = *(uint2*)hh;
    *(uint2*)(g_prP_l + i4*4) = *(uint2*)ll;
}

__global__ void k_maxpool(const float* __restrict__ out, float* __restrict__ pooled)
{
    int b = blockIdx.y;
    int d = blockIdx.x * blockDim.x + threadIdx.x;
    if (d >= DMODEL) return;
    const float* p = out + (size_t)b * LSEQ * DMODEL + d;
    float m = -FLT_MAX;
    for (int l = 0; l < LSEQ; l++) m = fmaxf(m, p[(size_t)l * DMODEL]);
    pooled[b * DMODEL + d] = m;
}

// ------------------------- launch -------------------------
extern "C" void kernel_launch(void* const* d_in, const int* in_sizes, int n_in,
                              void* d_out, int out_size)
{
    const int*   ids    = (const int*)  d_in[0];
    const float* emb    = (const float*)d_in[1];
    const float* rms_w  = (const float*)d_in[2];
    const float* W_in   = (const float*)d_in[3];
    const float* b_in   = (const float*)d_in[4];
    const float* conv_w = (const float*)d_in[5];
    const float* conv_b = (const float*)d_in[6];
    const float* W_cl   = (const float*)d_in[7];
    const float* b_cl   = (const float*)d_in[8];
    const float* fc1_w  = (const float*)d_in[9];
    const float* fc1_b  = (const float*)d_in[10];
    const float* fc2_w  = (const float*)d_in[11];
    const float* fc2_b  = (const float*)d_in[12];
    const float* fc3_w  = (const float*)d_in[13];
    const float* fc3_b  = (const float*)d_in[14];
    const float* W_D    = (const float*)d_in[16];
    const float* b_D    = (const float*)d_in[17];
    const float* W_out  = (const float*)d_in[18];
    const float* b_out  = (const float*)d_in[19];
    float* out = (float*)d_out;

    cudaFuncSetAttribute(k_tcW<0,false>, cudaFuncAttributeMaxDynamicSharedMemorySize, WSMEM);
    cudaFuncSetAttribute(k_tcW<0,true >, cudaFuncAttributeMaxDynamicSharedMemorySize, WSMEM);
    cudaFuncSetAttribute(k_tcW<1,true >, cudaFuncAttributeMaxDynamicSharedMemorySize, WSMEM);
    cudaFuncSetAttribute(k_tcW<3,false>, cudaFuncAttributeMaxDynamicSharedMemorySize, WSMEM);
    cudaFuncSetAttribute(k_tcN,          cudaFuncAttributeMaxDynamicSharedMemorySize, NSMEM);

    bf16 *xnh, *xnl, *xcah, *xcal, *xcoh, *xcol, *prh, *prl;
    bf16 *w15h, *w15l, *wclh, *wcll, *f17h, *f17l, *woh, *wol;
    bf16 *cah, *cal, *cbh, *cbl;
    float *pxpr, *pxco, *pdl, *pb15, *pb17;
    cudaGetSymbolAddress((void**)&xnh,  g_xnP_h);  cudaGetSymbolAddress((void**)&xnl,  g_xnP_l);
    cudaGetSymbolAddress((void**)&xcah, g_xcaP_h); cudaGetSymbolAddress((void**)&xcal, g_xcaP_l);
    cudaGetSymbolAddress((void**)&xcoh, g_xcoP_h); cudaGetSymbolAddress((void**)&xcol, g_xcoP_l);
    cudaGetSymbolAddress((void**)&prh,  g_prP_h);  cudaGetSymbolAddress((void**)&prl,  g_prP_l);
    cudaGetSymbolAddress((void**)&w15h, g_W15_h);  cudaGetSymbolAddress((void**)&w15l, g_W15_l);
    cudaGetSymbolAddress((void**)&wclh, g_WclS_h); cudaGetSymbolAddress((void**)&wcll, g_WclS_l);
    cudaGetSymbolAddress((void**)&f17h, g_f17_h);  cudaGetSymbolAddress((void**)&f17l, g_f17_l);
    cudaGetSymbolAddress((void**)&woh,  g_WoS_h);  cudaGetSymbolAddress((void**)&wol,  g_WoS_l);
    cudaGetSymbolAddress((void**)&cah,  g_cA_h);   cudaGetSymbolAddress((void**)&cal,  g_cA_l);
    cudaGetSymbolAddress((void**)&cbh,  g_cB_h);   cudaGetSymbolAddress((void**)&cbl,  g_cB_l);
    cudaGetSymbolAddress((void**)&pxpr, g_xpr);
    cudaGetSymbolAddress((void**)&pxco, g_xco);
    cudaGetSymbolAddress((void**)&pdl,  g_dl);
    cudaGetSymbolAddress((void**)&pb15, g_b15);
    cudaGetSymbolAddress((void**)&pb17, g_b17);

    // weight packs
    k_wsplit2<<<(DMODEL*D2V/4)/256, 256>>>(W_in,  w15h, w15l, D2V, N2X, 0);
    k_wsplit2<<<(DMODEL*D2V/4)/256, 256>>>(W_D,   w15h, w15l, D2V, N2X, D2V);
    k_wsplit2<<<(D2V*D2V/4)/256,    256>>>(W_cl,  wclh, wcll, D2V, D2V, 0);
    k_wsplit2<<<(D2V*D2V/4)/256,    256>>>(fc1_w, f17h, f17l, D2V, N17, 0);
    k_wsplit2<<<(D2V*NSTATE/4)/256, 256>>>(fc2_w, f17h, f17l, NSTATE, N17, D2V);
    k_wsplit2<<<(D2V*NSTATE/4)/256, 256>>>(fc3_w, f17h, f17l, NSTATE, N17, D2V + NSTATE);
    k_wsplit2<<<(D2V*DMODEL/4)/256, 256>>>(W_out, woh,  wol,  DMODEL, DMODEL, 0);
    k_bcat<<<N2X/256, 256>>>(b_in, b_D);
    k_bcat17<<<N17/256, 256>>>(fc1_b, fc2_b, fc3_b);
    k_convA<<<dim3(LSEQ/256, LSEQ), 256>>>(conv_w);

    // embed + norms
    k_embed<<<ROWS, 256>>>(ids, emb);
    k_samplestats<<<BATCH, 256>>>();
    k_norm<<<ROWS, 256>>>(rms_w);

    // GEMM1+5: [xp | xres_raw] = xn @ [W_in | W_D] + [b_in | b_D]
    k_tcW<0,false><<<dim3(N2X/256, ROWS/128, 1), 256, WSMEM>>>(
        xnh, xnl, w15h, w15l, pb15, nullptr, pxpr, nullptr, nullptr,
        DMODEL, N2X, 0, 0, 0);

    k_convB<<<dim3(LSEQ, 3*BATCH), 384>>>();

    // GEMM2 (conv): xca = silu(cA @ cB + conv_b[row]), split only
    k_tcW<1,true><<<dim3(D2V/256, LSEQ/128, BATCH), 256, WSMEM>>>(
        cah, cal, cbh, cbl, nullptr, conv_b, nullptr, xcah, xcal,
        K3, D2V, 0, (long)K3*D2V, (long)LSEQ*D2V);

    // GEMM3: xco = xca @ W_cl + b_cl (float + split)
    k_tcW<0,true><<<dim3(D2V/256, ROWS/128, 1), 256, WSMEM>>>(
        xcah, xcal, wclh, wcll, b_cl, nullptr, pxco, xcoh, xcol,
        D2V, D2V, 0, 0, 0);

    // GEMM4 fused: [delta | Bm | Cm | pad] = xco @ [fc1|fc2|fc3|0], softplus on cols < D2V
    k_tcW<3,false><<<dim3(N17/256, ROWS/128, 1), 256, WSMEM>>>(
        xcoh, xcol, f17h, f17l, pb17, nullptr, pdl, nullptr, nullptr,
        D2V, N17, 0, 0, 0);

    // s[row]
    k_s<<<ROWS, 32>>>();

    // prod (split for GEMM6)
    k_prod<<<(ROWS * D2V / 4) / 256, 256>>>();

    // GEMM6: out = prod @ W_out + b_out
    k_tcN<<<dim3(DMODEL/BN, ROWS/BM, 1), 256, NSMEM>>>(
        prh, prl, woh, wol, b_out, out, D2V, DMODEL);

    if (out_size >= ROWS * DMODEL + BATCH * DMODEL)
        k_maxpool<<<dim3((DMODEL + 255) / 256, BATCH), 256>>>(out, out + (size_t)ROWS * DMODEL);
}